// round 12
// baseline (speedup 1.0000x reference)
#include <cuda_runtime.h>
#include <cuda_bf16.h>
#include <cstdint>
#include <cstddef>

typedef unsigned long long ull;
typedef uint32_t u32;

#define BN 4
#define CH 64
#define NPIX 4096

// ---------- scratch ----------
__device__ float g_rk[BN*CH*NPIX];
__device__ float g_ik[BN*CH*NPIX];
__device__ float g_rr[BN*CH*NPIX];
__device__ float g_ir[BN*CH*NPIX];
// split-bf16 operands (u32 = bf16x2), pitch 36 u32 (72 bf16)
__device__ u32 g_Khi[4*4096*36];
__device__ u32 g_Klo[4*4096*36];
__device__ u32 g_Vhi[8*4096*36];
// repacked weights [conv][ci][k][oc64]
__device__ float g_Wp[294912];

// ---------- helpers ----------
__device__ __forceinline__ ull pk2(float a, float b) {
    ull r; asm("mov.b64 %0, {%1, %2};" : "=l"(r) : "f"(a), "f"(b)); return r;
}
__device__ __forceinline__ float2 up2(ull v) {
    float2 f; asm("mov.b64 {%0, %1}, %2;" : "=f"(f.x), "=f"(f.y) : "l"(v)); return f;
}
__device__ __forceinline__ void fma2(ull& d, ull a, ull b) {
    asm("fma.rn.f32x2 %0, %1, %2, %0;" : "+l"(d) : "l"(a), "l"(b));
}
__device__ __forceinline__ u32 s2u(const void* p) {
    u32 a; asm("{ .reg .u64 t; cvta.to.shared.u64 t, %1; cvt.u32.u64 %0, t; }" : "=r"(a) : "l"(p));
    return a;
}
__device__ __forceinline__ u32 cvt2bf(float hi, float lo) {   // {lo16=lo, hi16=hi}
    u32 r; asm("cvt.rn.bf16x2.f32 %0, %1, %2;" : "=r"(r) : "f"(hi), "f"(lo)); return r;
}
__device__ __forceinline__ float lo16f(u32 u) { return __uint_as_float(u << 16); }
__device__ __forceinline__ float hi16f(u32 u) { return __uint_as_float(u & 0xFFFF0000u); }
__device__ __forceinline__ void ldsm4(u32& r0, u32& r1, u32& r2, u32& r3, u32 addr) {
    asm volatile("ldmatrix.sync.aligned.m8n8.x4.shared.b16 {%0,%1,%2,%3}, [%4];"
                 : "=r"(r0), "=r"(r1), "=r"(r2), "=r"(r3) : "r"(addr));
}

// ============================================================
// weight repack: w[oc][ci][3x3] -> g_Wp[off + (ci*9+k)*64 + oc]
// ============================================================
struct WPack { const float* w[6]; int cin[6]; int off[6]; };
__global__ void __launch_bounds__(256) wrep_k(WPack W) {
    const int cv = blockIdx.z;
    const int elems = W.cin[cv] * 576;
    const float* src = W.w[cv];
    float* dst = g_Wp + W.off[cv];
    for (int i = blockIdx.x * 256 + threadIdx.x; i < elems; i += 288 * 256) {
        int oc = i & 63, t = i >> 6;
        int k = t % 9, ci = t / 9;
        dst[i] = src[(oc * W.cin[cv] + ci) * 9 + k];
    }
}

// ============================================================
// conv3x3+BN+ReLU v2: 32x16 px tile, 2 px/thread, OCB oc/block,
// 4 ci/stage, all 16B cp.async, repacked weights.
// mode 0: fp32 out. mode 1: split-bf16 K. mode 2: V hi.
// ============================================================
struct CArg { const float* inA; const float* inB;
              const float* s; const float* bb; float* out;
              int cin; int mode; int av; int woff; };
struct CPack { CArg c[5]; };

template<int OCB>
__global__ void __launch_bounds__(256) conv_k(CPack P) {
    constexpr int GR = 64 / OCB;
    constexpr int NWV = 9 * OCB;
    constexpr int PV = 9 * OCB / 4;
    __shared__ __align__(16) float tile[2][4][720];   // 18 x 40
    __shared__ __align__(16) float wsm[2][4][9 * OCB];
    const int tid = threadIdx.x;
    const int tx = tid & 15, ty = tid >> 4;
    const int z = blockIdx.z;
    const CArg a = P.c[z / (4 * GR)];
    const int b   = (z / GR) & 3;
    const int ocb = (z % GR) * OCB;
    const int ox0 = blockIdx.x << 5, oy0 = blockIdx.y << 4;
    const int oy = oy0 + ty;
    const int S = a.cin >> 2;
    const bool wide = (a.cin == 128);

    const float* baseA = a.inA + (size_t)b * 64 * 4096;
    const float* baseB = wide ? a.inB + (size_t)b * 64 * 4096 : baseA;
    const float* wbase = g_Wp + a.woff;

    // ---- hoist tile-load slots (720 16B vecs per stage) ----
    u32 t_sa[3], t_go[3], t_ok[3]; int t_pl[3];
#pragma unroll
    for (int s = 0; s < 3; s++) {
        int i = tid + s * 256;
        if (i >= 720) i = 0;
        int pl = i / 180, r2 = i - pl * 180;
        int r = r2 / 10, v = r2 - r * 10;
        int iy = oy0 - 1 + r, x0 = ox0 - 4 + 4 * v;
        bool ib = iy >= 0 && iy < 64 && x0 >= 0 && x0 <= 60;
        t_pl[s] = pl;
        t_ok[s] = ib ? 16u : 0u;
        t_go[s] = ib ? (u32)(iy * 64 + x0) : 0u;
        t_sa[s] = s2u(&tile[0][pl][r * 40 + 4 * v]);
    }
    // ---- hoist weight slot ----
    const bool wact = tid < NWV;
    u32 w_go = 0, w_sa = 0;
    {
        int j = wact ? tid : 0;
        int pl = j / PV, rem = j - pl * PV;
        int k = rem / (OCB / 4), q = rem - k * (OCB / 4);
        w_go = (u32)(pl * 576 + k * 64 + ocb + 4 * q);
        w_sa = s2u(&wsm[0][pl][k * OCB + 4 * q]);
    }

    ull acc0[OCB / 2], acc1[OCB / 2];
#pragma unroll
    for (int p = 0; p < OCB / 2; p++) { acc0[p] = 0ull; acc1[p] = 0ull; }

    for (int st = 0; st <= S; st++) {
        if (st < S) {
            const int c0 = st * 4;
            const u32 tadd = (st & 1) ? 11520u : 0u;
            const u32 wadd = (st & 1) ? (u32)(144 * OCB) : 0u;
#pragma unroll
            for (int s = 0; s < 3; s++) {
                if (s == 2 && tid >= 208) break;
                int ci = c0 + t_pl[s];
                const float* gp = ((wide && ci >= 64) ? baseB : baseA)
                                  + (ci & 63) * 4096 + t_go[s];
                asm volatile("cp.async.ca.shared.global [%0], [%1], 16, %2;"
                             :: "r"(t_sa[s] + tadd), "l"(gp), "r"(t_ok[s]));
            }
            if (wact) {
                const float* gp = wbase + w_go + c0 * 576;
                asm volatile("cp.async.ca.shared.global [%0], [%1], 16;"
                             :: "r"(w_sa + wadd), "l"(gp));
            }
            asm volatile("cp.async.commit_group;" ::: "memory");
        }
        if (st == 0) continue;
        if (st < S) asm volatile("cp.async.wait_group 1;" ::: "memory");
        else        asm volatile("cp.async.wait_group 0;" ::: "memory");
        __syncthreads();
        const int sb = (st - 1) & 1;
#pragma unroll
        for (int pl = 0; pl < 4; pl++) {
            float v0[9], v1[9];
#pragma unroll
            for (int ky = 0; ky < 3; ky++)
#pragma unroll
                for (int kx = 0; kx < 3; kx++) {
                    int idx = (ty + ky) * 40 + tx + kx + 3;
                    v0[ky * 3 + kx] = tile[sb][pl][idx];
                    v1[ky * 3 + kx] = tile[sb][pl][idx + 16];
                }
#pragma unroll
            for (int k = 0; k < 9; k++) {
                ull vv0 = pk2(v0[k], v0[k]);
                ull vv1 = pk2(v1[k], v1[k]);
#pragma unroll
                for (int q = 0; q < OCB / 4; q++) {
                    ulonglong2 w2 = *(const ulonglong2*)(&wsm[sb][pl][k * OCB + 4 * q]);
                    fma2(acc0[2 * q],     vv0, w2.x);
                    fma2(acc0[2 * q + 1], vv0, w2.y);
                    fma2(acc1[2 * q],     vv1, w2.x);
                    fma2(acc1[2 * q + 1], vv1, w2.y);
                }
            }
        }
        __syncthreads();
    }

    float vals[2][OCB];
#pragma unroll
    for (int p = 0; p < OCB / 2; p++) {
        float2 o0 = up2(acc0[p]), o1 = up2(acc1[p]);
        float s0 = a.s[ocb + 2*p], s1 = a.s[ocb + 2*p + 1];
        float b0 = a.bb[ocb + 2*p], b1 = a.bb[ocb + 2*p + 1];
        vals[0][2*p]   = fmaxf(o0.x * s0 + b0, 0.f);
        vals[0][2*p+1] = fmaxf(o0.y * s1 + b1, 0.f);
        vals[1][2*p]   = fmaxf(o1.x * s0 + b0, 0.f);
        vals[1][2*p+1] = fmaxf(o1.y * s1 + b1, 0.f);
    }
#pragma unroll
    for (int px = 0; px < 2; px++) {
        const int ox = ox0 + tx + px * 16;
        if (a.mode == 0) {
#pragma unroll
            for (int j = 0; j < OCB; j++)
                a.out[(((size_t)b * 64 + ocb + j) * 64 + oy) * 64 + ox] = vals[px][j];
        } else if (a.mode == 1) {
            const size_t nbase = ((size_t)b * 4096 + oy * 64 + ox) * 36 + (ocb >> 1);
#pragma unroll
            for (int p = 0; p < OCB / 2; p++) {
                u32 h = cvt2bf(vals[px][2*p+1], vals[px][2*p]);
                u32 l = cvt2bf(vals[px][2*p+1] - hi16f(h), vals[px][2*p] - lo16f(h));
                g_Khi[nbase + p] = h;
                g_Klo[nbase + p] = l;
            }
        } else {
            const int lane = tid & 31;
            const int np = ox >> 1;
#pragma unroll
            for (int j = 0; j < OCB; j++) {
                float v = vals[px][j];
                float vp = __shfl_xor_sync(0xffffffffu, v, 1);
                if (!(lane & 1)) {
                    size_t idx = (((size_t)(a.av * 4 + b) * 64 + oy) * 64 + ocb + j) * 36 + np;
                    g_Vhi[idx] = cvt2bf(vp, v);
                }
            }
        }
    }
}

// ============================================================
// flash attention: warp mma, S 3-term / PV 2-term split-bf16,
// ldmatrix.x4 fragment loads, m-tile 128, 256 thr,
// fixed-shift softmax, 3-stage pipeline. grid (32, 4, 2)
// ============================================================
#define MMA(d, a, b0_, b1_) \
    asm volatile("mma.sync.aligned.m16n8k16.row.col.f32.bf16.bf16.f32 " \
        "{%0,%1,%2,%3}, {%4,%5,%6,%7}, {%8,%9}, {%0,%1,%2,%3};" \
        : "+f"((d)[0]), "+f"((d)[1]), "+f"((d)[2]), "+f"((d)[3]) \
        : "r"((a)[0]), "r"((a)[1]), "r"((a)[2]), "r"((a)[3]), "r"(b0_), "r"(b1_))

#define STG_BYTES 27648u     // KH 9216 | KL 9216 | VH 9216
#define ATT_SMEM 82944u      // 3 buffers; Q staged over buf1/2

__device__ __forceinline__ void fetch_chunk(u32 sbase, int tid, int nt,
        const u32* kh, const u32* kl, const u32* vh) {
    const u32 off = (u32)nt * 2304u;
#pragma unroll
    for (int k = 0; k < 7; k++) {
        int idx = tid + k * 256;          // 0..1727
        if (k == 6 && idx >= 1728) break;
        int r = idx / 576, l = idx - r * 576;
        const u32* gp = (r == 0 ? kh : r == 1 ? kl : vh) + off + l * 4;
        asm volatile("cp.async.cg.shared.global [%0], [%1], 16;"
                     :: "r"(sbase + r * 9216u + l * 16u), "l"(gp));
    }
    asm volatile("cp.async.commit_group;" ::: "memory");
}

__global__ void __launch_bounds__(256) attn_k(const float* __restrict__ x,
                                              const float* __restrict__ y,
                                              const float* __restrict__ g1,
                                              const float* __restrict__ g2) {
    extern __shared__ char smc[];
    float* Qs = (float*)(smc + STG_BYTES);   // overlays buf1/2
    const u32 sbA = s2u(smc);
    const int tid = threadIdx.x;
    const int w = tid >> 5, lane = tid & 31;
    const int qr = lane >> 2, qc2 = (lane & 3) * 2;
    const int m0 = blockIdx.x * 128, b = blockIdx.y, a = blockIdx.z;

    // ldmatrix per-lane offset: matrix idx = lane>>3
    //   m0/m1: rows 0-7 (cols +0 / +16B); m2/m3: rows 8-15
    const u32 lmOff = (((lane >> 4) & 1) * 8 + (lane & 7)) * 144u
                    + ((lane >> 3) & 1) * 16u;

    const size_t boff = (size_t)b * CH * NPIX;
    const float* Aq  = (a ? g_ik : g_rk) + boff;
    const float* res = (a ? x : y) + boff;
    float* outp      = (a ? g_ir : g_rr) + boff;
    const float gamma = a ? g2[0] : g1[0];
    const u32* kh = g_Khi + (size_t)b * 147456;
    const u32* kl = g_Klo + (size_t)b * 147456;
    const u32* vh = g_Vhi + (size_t)(a * 4 + b) * 147456;

    // fetch chunk0 -> buf0; stage Q [m][c] fp32 over buf1/2
    fetch_chunk(sbA, tid, 0, kh, kl, vh);
    for (int i = tid; i < 8192; i += 256) {
        int m = i & 127, c = i >> 7;
        Qs[m * 68 + c] = Aq[(size_t)c * NPIX + m0 + m];
    }
    __syncthreads();

    // Q fragments hi/lo (row-major A)
    u32 ah[4][4], al[4][4];
    const int r0 = w * 16 + qr;
#pragma unroll
    for (int j = 0; j < 4; j++) {
        int c0 = j * 16 + qc2;
        float2 fs[4] = { *(float2*)(Qs + r0 * 68 + c0),
                         *(float2*)(Qs + (r0 + 8) * 68 + c0),
                         *(float2*)(Qs + r0 * 68 + c0 + 8),
                         *(float2*)(Qs + (r0 + 8) * 68 + c0 + 8) };
#pragma unroll
        for (int r = 0; r < 4; r++) {
            u32 h = cvt2bf(fs[r].y, fs[r].x);
            ah[j][r] = h;
            al[j][r] = cvt2bf(fs[r].y - hi16f(h), fs[r].x - lo16f(h));
        }
    }
    __syncthreads();   // all Q reads done before buf1/2 prefetches
    fetch_chunk(sbA + STG_BYTES, tid, 1, kh, kl, vh);
    fetch_chunk(sbA + 2 * STG_BYTES, tid, 2, kh, kl, vh);

    float O[8][4];
#pragma unroll
    for (int f = 0; f < 8; f++)
#pragma unroll
        for (int r = 0; r < 4; r++) O[f][r] = 0.f;
    float M0 = 0.f, M1 = 0.f, L0 = 0.f, L1 = 0.f;

    for (int nt = 0; nt < 64; nt++) {
        if (nt < 62)      asm volatile("cp.async.wait_group 2;" ::: "memory");
        else if (nt == 62) asm volatile("cp.async.wait_group 1;" ::: "memory");
        else              asm volatile("cp.async.wait_group 0;" ::: "memory");
        __syncthreads();
        const u32 sbufU = sbA + (u32)(nt % 3) * STG_BYTES;
        const u32 sK = sbufU + lmOff;            // K hi (lo at +9216)
        const u32 sV = sbufU + 18432u + lmOff;   // V hi

        // ---- S = Q K^T, 3-term split, ldmatrix loads ----
        float S[8][4];
#pragma unroll
        for (int f = 0; f < 8; f++)
#pragma unroll
            for (int r = 0; r < 4; r++) S[f][r] = 0.f;
#pragma unroll
        for (int j = 0; j < 4; j++) {
#pragma unroll
            for (int f2 = 0; f2 < 4; f2++) {
                u32 h0, h1, h2, h3, l0, l1, l2, l3;
                ldsm4(h0, h1, h2, h3, sK + f2 * 2304u + j * 32u);
                ldsm4(l0, l1, l2, l3, sK + 9216u + f2 * 2304u + j * 32u);
                MMA(S[2*f2],   ah[j], h0, h1);
                MMA(S[2*f2],   al[j], h0, h1);
                MMA(S[2*f2],   ah[j], l0, l1);
                MMA(S[2*f2+1], ah[j], h2, h3);
                MMA(S[2*f2+1], al[j], h2, h3);
                MMA(S[2*f2+1], ah[j], l2, l3);
            }
        }

        // ---- fixed-shift softmax (chunk 0 sets shift) ----
        if (nt == 0) {
            float mx0 = -1e30f, mx1 = -1e30f;
#pragma unroll
            for (int f = 0; f < 8; f++) {
                mx0 = fmaxf(mx0, fmaxf(S[f][0], S[f][1]));
                mx1 = fmaxf(mx1, fmaxf(S[f][2], S[f][3]));
            }
            mx0 = fmaxf(mx0, __shfl_xor_sync(0xffffffffu, mx0, 1));
            mx0 = fmaxf(mx0, __shfl_xor_sync(0xffffffffu, mx0, 2));
            mx1 = fmaxf(mx1, __shfl_xor_sync(0xffffffffu, mx1, 1));
            mx1 = fmaxf(mx1, __shfl_xor_sync(0xffffffffu, mx1, 2));
            M0 = mx0; M1 = mx1;
        }
#pragma unroll
        for (int f = 0; f < 8; f++) {
            S[f][0] = __expf(S[f][0] - M0); S[f][1] = __expf(S[f][1] - M0);
            S[f][2] = __expf(S[f][2] - M1); S[f][3] = __expf(S[f][3] - M1);
            L0 += S[f][0] + S[f][1];
            L1 += S[f][2] + S[f][3];
        }

        // ---- O += P V^T (2-term), ldmatrix V loads ----
#pragma unroll
        for (int j2 = 0; j2 < 4; j2++) {
            u32 ph[4], pl2[4];
#pragma unroll
            for (int h2 = 0; h2 < 2; h2++) {
                float p0a = S[2*j2][2*h2],   p1a = S[2*j2][2*h2+1];
                float p0b = S[2*j2+1][2*h2], p1b = S[2*j2+1][2*h2+1];
                u32 hA = cvt2bf(p1a, p0a);
                u32 hB = cvt2bf(p1b, p0b);
                ph[h2]      = hA;
                ph[h2 + 2]  = hB;
                pl2[h2]     = cvt2bf(p1a - hi16f(hA), p0a - lo16f(hA));
                pl2[h2 + 2] = cvt2bf(p1b - hi16f(hB), p0b - lo16f(hB));
            }
#pragma unroll
            for (int q = 0; q < 4; q++) {
                u32 v0, v1, v2, v3;
                ldsm4(v0, v1, v2, v3, sV + q * 2304u + j2 * 32u);
                MMA(O[2*q],   ph,  v0, v1);
                MMA(O[2*q],   pl2, v0, v1);
                MMA(O[2*q+1], ph,  v2, v3);
                MMA(O[2*q+1], pl2, v2, v3);
            }
        }
        __syncthreads();
        if (nt + 3 < 64)
            fetch_chunk(sbA + (u32)(nt % 3) * STG_BYTES, tid, nt + 3, kh, kl, vh);
    }

    // ---- final L reduction (quad) + epilogue ----
    L0 += __shfl_xor_sync(0xffffffffu, L0, 1);
    L0 += __shfl_xor_sync(0xffffffffu, L0, 2);
    L1 += __shfl_xor_sync(0xffffffffu, L1, 1);
    L1 += __shfl_xor_sync(0xffffffffu, L1, 2);
    float i0 = 1.0f / L0, i1 = 1.0f / L1;
    const int mA = m0 + r0, mB = mA + 8;
#pragma unroll
    for (int fc = 0; fc < 8; fc++) {
        int c0 = fc * 8 + qc2;
        size_t iA0 = (size_t)c0 * NPIX + mA;
        size_t iA1 = (size_t)(c0 + 1) * NPIX + mA;
        outp[iA0] = gamma * (O[fc][0] * i0) + res[iA0];
        outp[iA1] = gamma * (O[fc][1] * i0) + res[iA1];
        size_t iB0 = (size_t)c0 * NPIX + mB;
        size_t iB1 = (size_t)(c0 + 1) * NPIX + mB;
        outp[iB0] = gamma * (O[fc][2] * i1) + res[iB0];
        outp[iB1] = gamma * (O[fc][3] * i1) + res[iB1];
    }
}

// ============================================================
extern "C" void kernel_launch(void* const* d_in, const int* in_sizes, int n_in,
                              void* d_out, int out_size) {
    const float* x    = (const float*)d_in[0];
    const float* y    = (const float*)d_in[1];
    const float* q_w  = (const float*)d_in[2];
    const float* q_s  = (const float*)d_in[3];
    const float* q_b  = (const float*)d_in[4];
    const float* rk_w = (const float*)d_in[5];
    const float* rk_s = (const float*)d_in[6];
    const float* rk_b = (const float*)d_in[7];
    const float* rv_w = (const float*)d_in[8];
    const float* rv_s = (const float*)d_in[9];
    const float* rv_b = (const float*)d_in[10];
    const float* ik_w = (const float*)d_in[11];
    const float* ik_s = (const float*)d_in[12];
    const float* ik_b = (const float*)d_in[13];
    const float* iv_w = (const float*)d_in[14];
    const float* iv_s = (const float*)d_in[15];
    const float* iv_b = (const float*)d_in[16];
    const float* sr_w = (const float*)d_in[17];
    const float* sr_s = (const float*)d_in[18];
    const float* sr_b = (const float*)d_in[19];
    const float* g1   = (const float*)d_in[20];
    const float* g2   = (const float*)d_in[21];
    float* out = (float*)d_out;

    float *prk, *pik, *prr, *pir;
    cudaGetSymbolAddress((void**)&prk, g_rk);
    cudaGetSymbolAddress((void**)&pik, g_ik);
    cudaGetSymbolAddress((void**)&prr, g_rr);
    cudaGetSymbolAddress((void**)&pir, g_ir);

    cudaFuncSetAttribute(attn_k, cudaFuncAttributeMaxDynamicSharedMemorySize,
                         (int)ATT_SMEM);

    // repack weights: offsets in floats
    WPack wp = {};
    wp.w[0] = q_w;  wp.cin[0] = 128; wp.off[0] = 0;
    wp.w[1] = rk_w; wp.cin[1] = 64;  wp.off[1] = 73728;
    wp.w[2] = rv_w; wp.cin[2] = 64;  wp.off[2] = 110592;
    wp.w[3] = ik_w; wp.cin[3] = 64;  wp.off[3] = 147456;
    wp.w[4] = iv_w; wp.cin[4] = 64;  wp.off[4] = 184320;
    wp.w[5] = sr_w; wp.cin[5] = 128; wp.off[5] = 221184;
    wrep_k<<<dim3(288, 1, 6), 256>>>(wp);

    // producers (16 oc/block, 32x16 tile): Q->K split, rk/ik fp32, rv/iv V
    CPack pp = {};
    pp.c[0] = { x, y,       q_s,  q_b,  nullptr, 128, 1, 0, 0 };
    pp.c[1] = { x, nullptr, rk_s, rk_b, prk,      64, 0, 0, 73728 };
    pp.c[2] = { x, nullptr, rv_s, rv_b, nullptr,  64, 2, 0, 110592 };
    pp.c[3] = { y, nullptr, ik_s, ik_b, pik,      64, 0, 0, 147456 };
    pp.c[4] = { y, nullptr, iv_s, iv_b, nullptr,  64, 2, 1, 184320 };
    conv_k<16><<<dim3(2, 4, 80), 256>>>(pp);

    attn_k<<<dim3(32, 4, 2), 256, ATT_SMEM>>>(x, y, g1, g2);

    // final conv (8 oc/block -> 256 blocks)
    CPack ps = {};
    ps.c[0] = { prr, pir, sr_s, sr_b, out, 128, 0, 0, 221184 };
    conv_k<8><<<dim3(2, 4, 32), 256>>>(ps);
}

// round 14
// speedup vs baseline: 1.0260x; 1.0260x over previous
#include <cuda_runtime.h>
#include <cuda_fp16.h>
#include <cstdint>
#include <cstddef>

typedef unsigned long long ull;
typedef uint32_t u32;

#define BN 4
#define CH 64
#define NPIX 4096

// ---------- scratch ----------
__device__ float g_rk[BN*CH*NPIX];
__device__ float g_ik[BN*CH*NPIX];
__device__ float g_rr[BN*CH*NPIX];
__device__ float g_ir[BN*CH*NPIX];
// split-fp16 operands (u32 = f16x2), pitch 36 u32 (72 f16)
__device__ u32 g_Khi[4*4096*36];
__device__ u32 g_Klo[4*4096*36];
__device__ u32 g_Vhi[8*4096*36];
// repacked weights [conv][ci][k][oc64]
__device__ float g_Wp[294912];

// ---------- helpers ----------
__device__ __forceinline__ ull pk2(float a, float b) {
    ull r; asm("mov.b64 %0, {%1, %2};" : "=l"(r) : "f"(a), "f"(b)); return r;
}
__device__ __forceinline__ float2 up2(ull v) {
    float2 f; asm("mov.b64 {%0, %1}, %2;" : "=f"(f.x), "=f"(f.y) : "l"(v)); return f;
}
__device__ __forceinline__ void fma2(ull& d, ull a, ull b) {
    asm("fma.rn.f32x2 %0, %1, %2, %0;" : "+l"(d) : "l"(a), "l"(b));
}
__device__ __forceinline__ u32 s2u(const void* p) {
    u32 a; asm("{ .reg .u64 t; cvta.to.shared.u64 t, %1; cvt.u32.u64 %0, t; }" : "=r"(a) : "l"(p));
    return a;
}
__device__ __forceinline__ u32 pkh2(float lo, float hi) {   // f16x2 {x=lo, y=hi}
    __half2 h = __floats2half2_rn(lo, hi);
    return *(u32*)&h;
}
__device__ __forceinline__ float2 uph2(u32 v) {
    __half2 h = *(__half2*)&v;
    return __half22float2(h);
}
__device__ __forceinline__ void ldsm4(u32& r0, u32& r1, u32& r2, u32& r3, u32 addr) {
    asm volatile("ldmatrix.sync.aligned.m8n8.x4.shared.b16 {%0,%1,%2,%3}, [%4];"
                 : "=r"(r0), "=r"(r1), "=r"(r2), "=r"(r3) : "r"(addr));
}

// ============================================================
// weight repack: w[oc][ci][3x3] -> g_Wp[off + (ci*9+k)*64 + oc]
// ============================================================
struct WPack { const float* w[6]; int cin[6]; int off[6]; };
__global__ void __launch_bounds__(256) wrep_k(WPack W) {
    const int cv = blockIdx.z;
    const int elems = W.cin[cv] * 576;
    const float* src = W.w[cv];
    float* dst = g_Wp + W.off[cv];
    for (int i = blockIdx.x * 256 + threadIdx.x; i < elems; i += 288 * 256) {
        int oc = i & 63, t = i >> 6;
        int k = t % 9, ci = t / 9;
        dst[i] = src[(oc * W.cin[cv] + ci) * 9 + k];
    }
}

// ============================================================
// conv3x3+BN+ReLU: 32x16 px tile, 2 px/thread, OCB oc/block,
// 4 ci/stage, all 16B cp.async, repacked weights.
// mode 0: fp32 out. mode 1: split-fp16 K. mode 2: fp16 V.
// ============================================================
struct CArg { const float* inA; const float* inB;
              const float* s; const float* bb; float* out;
              int cin; int mode; int av; int woff; };
struct CPack { CArg c[5]; };

template<int OCB>
__global__ void __launch_bounds__(256) conv_k(CPack P) {
    constexpr int GR = 64 / OCB;
    constexpr int NWV = 9 * OCB;
    constexpr int PV = 9 * OCB / 4;
    __shared__ __align__(16) float tile[2][4][720];   // 18 x 40
    __shared__ __align__(16) float wsm[2][4][9 * OCB];
    const int tid = threadIdx.x;
    const int tx = tid & 15, ty = tid >> 4;
    const int z = blockIdx.z;
    const CArg a = P.c[z / (4 * GR)];
    const int b   = (z / GR) & 3;
    const int ocb = (z % GR) * OCB;
    const int ox0 = blockIdx.x << 5, oy0 = blockIdx.y << 4;
    const int oy = oy0 + ty;
    const int S = a.cin >> 2;
    const bool wide = (a.cin == 128);

    const float* baseA = a.inA + (size_t)b * 64 * 4096;
    const float* baseB = wide ? a.inB + (size_t)b * 64 * 4096 : baseA;
    const float* wbase = g_Wp + a.woff;

    // ---- hoist tile-load slots ----
    u32 t_sa[3], t_go[3], t_ok[3]; int t_pl[3];
#pragma unroll
    for (int s = 0; s < 3; s++) {
        int i = tid + s * 256;
        if (i >= 720) i = 0;
        int pl = i / 180, r2 = i - pl * 180;
        int r = r2 / 10, v = r2 - r * 10;
        int iy = oy0 - 1 + r, x0 = ox0 - 4 + 4 * v;
        bool ib = iy >= 0 && iy < 64 && x0 >= 0 && x0 <= 60;
        t_pl[s] = pl;
        t_ok[s] = ib ? 16u : 0u;
        t_go[s] = ib ? (u32)(iy * 64 + x0) : 0u;
        t_sa[s] = s2u(&tile[0][pl][r * 40 + 4 * v]);
    }
    // ---- hoist weight slot ----
    const bool wact = tid < NWV;
    u32 w_go = 0, w_sa = 0;
    {
        int j = wact ? tid : 0;
        int pl = j / PV, rem = j - pl * PV;
        int k = rem / (OCB / 4), q = rem - k * (OCB / 4);
        w_go = (u32)(pl * 576 + k * 64 + ocb + 4 * q);
        w_sa = s2u(&wsm[0][pl][k * OCB + 4 * q]);
    }

    ull acc0[OCB / 2], acc1[OCB / 2];
#pragma unroll
    for (int p = 0; p < OCB / 2; p++) { acc0[p] = 0ull; acc1[p] = 0ull; }

    for (int st = 0; st <= S; st++) {
        if (st < S) {
            const int c0 = st * 4;
            const u32 tadd = (st & 1) ? 11520u : 0u;
            const u32 wadd = (st & 1) ? (u32)(144 * OCB) : 0u;
#pragma unroll
            for (int s = 0; s < 3; s++) {
                if (s == 2 && tid >= 208) break;
                int ci = c0 + t_pl[s];
                const float* gp = ((wide && ci >= 64) ? baseB : baseA)
                                  + (ci & 63) * 4096 + t_go[s];
                asm volatile("cp.async.ca.shared.global [%0], [%1], 16, %2;"
                             :: "r"(t_sa[s] + tadd), "l"(gp), "r"(t_ok[s]));
            }
            if (wact) {
                const float* gp = wbase + w_go + c0 * 576;
                asm volatile("cp.async.ca.shared.global [%0], [%1], 16;"
                             :: "r"(w_sa + wadd), "l"(gp));
            }
            asm volatile("cp.async.commit_group;" ::: "memory");
        }
        if (st == 0) continue;
        if (st < S) asm volatile("cp.async.wait_group 1;" ::: "memory");
        else        asm volatile("cp.async.wait_group 0;" ::: "memory");
        __syncthreads();
        const int sb = (st - 1) & 1;
#pragma unroll
        for (int pl = 0; pl < 4; pl++) {
            float v0[9], v1[9];
#pragma unroll
            for (int ky = 0; ky < 3; ky++)
#pragma unroll
                for (int kx = 0; kx < 3; kx++) {
                    int idx = (ty + ky) * 40 + tx + kx + 3;
                    v0[ky * 3 + kx] = tile[sb][pl][idx];
                    v1[ky * 3 + kx] = tile[sb][pl][idx + 16];
                }
#pragma unroll
            for (int k = 0; k < 9; k++) {
                ull vv0 = pk2(v0[k], v0[k]);
                ull vv1 = pk2(v1[k], v1[k]);
#pragma unroll
                for (int q = 0; q < OCB / 4; q++) {
                    ulonglong2 w2 = *(const ulonglong2*)(&wsm[sb][pl][k * OCB + 4 * q]);
                    fma2(acc0[2 * q],     vv0, w2.x);
                    fma2(acc0[2 * q + 1], vv0, w2.y);
                    fma2(acc1[2 * q],     vv1, w2.x);
                    fma2(acc1[2 * q + 1], vv1, w2.y);
                }
            }
        }
        __syncthreads();
    }

    float vals[2][OCB];
#pragma unroll
    for (int p = 0; p < OCB / 2; p++) {
        float2 o0 = up2(acc0[p]), o1 = up2(acc1[p]);
        float s0 = a.s[ocb + 2*p], s1 = a.s[ocb + 2*p + 1];
        float b0 = a.bb[ocb + 2*p], b1 = a.bb[ocb + 2*p + 1];
        vals[0][2*p]   = fmaxf(o0.x * s0 + b0, 0.f);
        vals[0][2*p+1] = fmaxf(o0.y * s1 + b1, 0.f);
        vals[1][2*p]   = fmaxf(o1.x * s0 + b0, 0.f);
        vals[1][2*p+1] = fmaxf(o1.y * s1 + b1, 0.f);
    }
#pragma unroll
    for (int px = 0; px < 2; px++) {
        const int ox = ox0 + tx + px * 16;
        if (a.mode == 0) {
#pragma unroll
            for (int j = 0; j < OCB; j++)
                a.out[(((size_t)b * 64 + ocb + j) * 64 + oy) * 64 + ox] = vals[px][j];
        } else if (a.mode == 1) {
            // K: [b][n][cp], pair over c, fp16 hi/lo
            const size_t nbase = ((size_t)b * 4096 + oy * 64 + ox) * 36 + (ocb >> 1);
#pragma unroll
            for (int p = 0; p < OCB / 2; p++) {
                u32 h = pkh2(vals[px][2*p], vals[px][2*p+1]);
                float2 hf = uph2(h);
                u32 l = pkh2(vals[px][2*p] - hf.x, vals[px][2*p+1] - hf.y);
                g_Khi[nbase + p] = h;
                g_Klo[nbase + p] = l;
            }
        } else {
            // V: [av*4+b][nt=oy][c][np], pair over n, fp16
            const int lane = tid & 31;
            const int np = ox >> 1;
#pragma unroll
            for (int j = 0; j < OCB; j++) {
                float v = vals[px][j];
                float vp = __shfl_xor_sync(0xffffffffu, v, 1);
                if (!(lane & 1)) {
                    size_t idx = (((size_t)(a.av * 4 + b) * 64 + oy) * 64 + ocb + j) * 36 + np;
                    g_Vhi[idx] = pkh2(v, vp);
                }
            }
        }
    }
}

// ============================================================
// flash attention: warp mma fp16, S 3-term split / PV 1-term,
// ldmatrix.x4, m-tile 128, 256 thr, ONLINE softmax (P<=1, no
// fp16 overflow), 3-stage pipeline. grid (32, 4, 2)
// ============================================================
#define MMA(d, a, b0_, b1_) \
    asm volatile("mma.sync.aligned.m16n8k16.row.col.f32.f16.f16.f32 " \
        "{%0,%1,%2,%3}, {%4,%5,%6,%7}, {%8,%9}, {%0,%1,%2,%3};" \
        : "+f"((d)[0]), "+f"((d)[1]), "+f"((d)[2]), "+f"((d)[3]) \
        : "r"((a)[0]), "r"((a)[1]), "r"((a)[2]), "r"((a)[3]), "r"(b0_), "r"(b1_))

#define STG_BYTES 27648u     // KH 9216 | KL 9216 | VH 9216
#define ATT_SMEM 82944u      // 3 buffers; Q staged over buf1/2

__device__ __forceinline__ void fetch_chunk(u32 sbase, int tid, int nt,
        const u32* kh, const u32* kl, const u32* vh) {
    const u32 off = (u32)nt * 2304u;
#pragma unroll
    for (int k = 0; k < 7; k++) {
        int idx = tid + k * 256;          // 0..1727
        if (k == 6 && idx >= 1728) break;
        int r = idx / 576, l = idx - r * 576;
        const u32* gp = (r == 0 ? kh : r == 1 ? kl : vh) + off + l * 4;
        asm volatile("cp.async.cg.shared.global [%0], [%1], 16;"
                     :: "r"(sbase + r * 9216u + l * 16u), "l"(gp));
    }
    asm volatile("cp.async.commit_group;" ::: "memory");
}

__global__ void __launch_bounds__(256) attn_k(const float* __restrict__ x,
                                              const float* __restrict__ y,
                                              const float* __restrict__ g1,
                                              const float* __restrict__ g2) {
    extern __shared__ char smc[];
    float* Qs = (float*)(smc + STG_BYTES);   // overlays buf1/2
    const u32 sbA = s2u(smc);
    const int tid = threadIdx.x;
    const int w = tid >> 5, lane = tid & 31;
    const int qr = lane >> 2, qc2 = (lane & 3) * 2;
    const int m0 = blockIdx.x * 128, b = blockIdx.y, a = blockIdx.z;

    // ldmatrix per-lane offset
    const u32 lmOff = (((lane >> 4) & 1) * 8 + (lane & 7)) * 144u
                    + ((lane >> 3) & 1) * 16u;

    const size_t boff = (size_t)b * CH * NPIX;
    const float* Aq  = (a ? g_ik : g_rk) + boff;
    const float* res = (a ? x : y) + boff;
    float* outp      = (a ? g_ir : g_rr) + boff;
    const float gamma = a ? g2[0] : g1[0];
    const u32* kh = g_Khi + (size_t)b * 147456;
    const u32* kl = g_Klo + (size_t)b * 147456;
    const u32* vh = g_Vhi + (size_t)(a * 4 + b) * 147456;

    // fetch chunk0 -> buf0; stage Q [m][c] fp32 over buf1/2
    fetch_chunk(sbA, tid, 0, kh, kl, vh);
    for (int i = tid; i < 8192; i += 256) {
        int m = i & 127, c = i >> 7;
        Qs[m * 68 + c] = Aq[(size_t)c * NPIX + m0 + m];
    }
    __syncthreads();

    // Q fragments hi/lo fp16 (row-major A)
    u32 ah[4][4], al[4][4];
    const int r0 = w * 16 + qr;
#pragma unroll
    for (int j = 0; j < 4; j++) {
        int c0 = j * 16 + qc2;
        float2 fs[4] = { *(float2*)(Qs + r0 * 68 + c0),
                         *(float2*)(Qs + (r0 + 8) * 68 + c0),
                         *(float2*)(Qs + r0 * 68 + c0 + 8),
                         *(float2*)(Qs + (r0 + 8) * 68 + c0 + 8) };
#pragma unroll
        for (int r = 0; r < 4; r++) {
            u32 h = pkh2(fs[r].x, fs[r].y);
            float2 hf = uph2(h);
            ah[j][r] = h;
            al[j][r] = pkh2(fs[r].x - hf.x, fs[r].y - hf.y);
        }
    }
    __syncthreads();   // all Q reads done before buf1/2 prefetches
    fetch_chunk(sbA + STG_BYTES, tid, 1, kh, kl, vh);
    fetch_chunk(sbA + 2 * STG_BYTES, tid, 2, kh, kl, vh);

    float O[8][4];
#pragma unroll
    for (int f = 0; f < 8; f++)
#pragma unroll
        for (int r = 0; r < 4; r++) O[f][r] = 0.f;
    float M0 = -1e30f, M1 = -1e30f, L0 = 0.f, L1 = 0.f;

    for (int nt = 0; nt < 64; nt++) {
        if (nt < 62)      asm volatile("cp.async.wait_group 2;" ::: "memory");
        else if (nt == 62) asm volatile("cp.async.wait_group 1;" ::: "memory");
        else              asm volatile("cp.async.wait_group 0;" ::: "memory");
        __syncthreads();
        const u32 sbufU = sbA + (u32)(nt % 3) * STG_BYTES;
        const u32 sK = sbufU + lmOff;            // K hi (lo at +9216)
        const u32 sV = sbufU + 18432u + lmOff;   // V

        // ---- S = Q K^T, 3-term fp16 split ----
        float S[8][4];
#pragma unroll
        for (int f = 0; f < 8; f++)
#pragma unroll
            for (int r = 0; r < 4; r++) S[f][r] = 0.f;
#pragma unroll
        for (int j = 0; j < 4; j++) {
#pragma unroll
            for (int f2 = 0; f2 < 4; f2++) {
                u32 h0, h1, h2, h3, l0, l1, l2, l3;
                ldsm4(h0, h1, h2, h3, sK + f2 * 2304u + j * 32u);
                ldsm4(l0, l1, l2, l3, sK + 9216u + f2 * 2304u + j * 32u);
                MMA(S[2*f2],   ah[j], h0, h1);
                MMA(S[2*f2],   al[j], h0, h1);
                MMA(S[2*f2],   ah[j], l0, l1);
                MMA(S[2*f2+1], ah[j], h2, h3);
                MMA(S[2*f2+1], al[j], h2, h3);
                MMA(S[2*f2+1], ah[j], l2, l3);
            }
        }

        // ---- online softmax (P <= 1 always; fp16-safe) ----
        {
            float mx0 = -1e30f, mx1 = -1e30f;
#pragma unroll
            for (int f = 0; f < 8; f++) {
                mx0 = fmaxf(mx0, fmaxf(S[f][0], S[f][1]));
                mx1 = fmaxf(mx1, fmaxf(S[f][2], S[f][3]));
            }
            mx0 = fmaxf(mx0, __shfl_xor_sync(0xffffffffu, mx0, 1));
            mx0 = fmaxf(mx0, __shfl_xor_sync(0xffffffffu, mx0, 2));
            mx1 = fmaxf(mx1, __shfl_xor_sync(0xffffffffu, mx1, 1));
            mx1 = fmaxf(mx1, __shfl_xor_sync(0xffffffffu, mx1, 2));
            float mn0 = fmaxf(M0, mx0), mn1 = fmaxf(M1, mx1);
            float sc0 = __expf(M0 - mn0), sc1 = __expf(M1 - mn1);
            M0 = mn0; M1 = mn1;
            L0 *= sc0; L1 *= sc1;
#pragma unroll
            for (int f = 0; f < 8; f++) {
                O[f][0] *= sc0; O[f][1] *= sc0;
                O[f][2] *= sc1; O[f][3] *= sc1;
            }
        }
#pragma unroll
        for (int f = 0; f < 8; f++) {
            S[f][0] = __expf(S[f][0] - M0); S[f][1] = __expf(S[f][1] - M0);
            S[f][2] = __expf(S[f][2] - M1); S[f][3] = __expf(S[f][3] - M1);
            L0 += S[f][0] + S[f][1];
            L1 += S[f][2] + S[f][3];
        }

        // ---- O += P V^T (1-term fp16, P in [0,1]) ----
#pragma unroll
        for (int j2 = 0; j2 < 4; j2++) {
            u32 ph[4];
            ph[0] = pkh2(S[2*j2][0],   S[2*j2][1]);
            ph[1] = pkh2(S[2*j2][2],   S[2*j2][3]);
            ph[2] = pkh2(S[2*j2+1][0], S[2*j2+1][1]);
            ph[3] = pkh2(S[2*j2+1][2], S[2*j2+1][3]);
#pragma unroll
            for (int q = 0; q < 4; q++) {
                u32 v0, v1, v2, v3;
                ldsm4(v0, v1, v2, v3, sV + q * 2304u + j2 * 32u);
                MMA(O[2*q],   ph, v0, v1);
                MMA(O[2*q+1], ph, v2, v3);
            }
        }
        __syncthreads();
        if (nt + 3 < 64)
            fetch_chunk(sbA + (u32)(nt % 3) * STG_BYTES, tid, nt + 3, kh, kl, vh);
    }

    // ---- final L reduction (quad) + epilogue ----
    L0 += __shfl_xor_sync(0xffffffffu, L0, 1);
    L0 += __shfl_xor_sync(0xffffffffu, L0, 2);
    L1 += __shfl_xor_sync(0xffffffffu, L1, 1);
    L1 += __shfl_xor_sync(0xffffffffu, L1, 2);
    float i0 = 1.0f / L0, i1 = 1.0f / L1;
    const int mA = m0 + r0, mB = mA + 8;
#pragma unroll
    for (int fc = 0; fc < 8; fc++) {
        int c0 = fc * 8 + qc2;
        size_t iA0 = (size_t)c0 * NPIX + mA;
        size_t iA1 = (size_t)(c0 + 1) * NPIX + mA;
        outp[iA0] = gamma * (O[fc][0] * i0) + res[iA0];
        outp[iA1] = gamma * (O[fc][1] * i0) + res[iA1];
        size_t iB0 = (size_t)c0 * NPIX + mB;
        size_t iB1 = (size_t)(c0 + 1) * NPIX + mB;
        outp[iB0] = gamma * (O[fc][2] * i1) + res[iB0];
        outp[iB1] = gamma * (O[fc][3] * i1) + res[iB1];
    }
}

// ============================================================
extern "C" void kernel_launch(void* const* d_in, const int* in_sizes, int n_in,
                              void* d_out, int out_size) {
    const float* x    = (const float*)d_in[0];
    const float* y    = (const float*)d_in[1];
    const float* q_w  = (const float*)d_in[2];
    const float* q_s  = (const float*)d_in[3];
    const float* q_b  = (const float*)d_in[4];
    const float* rk_w = (const float*)d_in[5];
    const float* rk_s = (const float*)d_in[6];
    const float* rk_b = (const float*)d_in[7];
    const float* rv_w = (const float*)d_in[8];
    const float* rv_s = (const float*)d_in[9];
    const float* rv_b = (const float*)d_in[10];
    const float* ik_w = (const float*)d_in[11];
    const float* ik_s = (const float*)d_in[12];
    const float* ik_b = (const float*)d_in[13];
    const float* iv_w = (const float*)d_in[14];
    const float* iv_s = (const float*)d_in[15];
    const float* iv_b = (const float*)d_in[16];
    const float* sr_w = (const float*)d_in[17];
    const float* sr_s = (const float*)d_in[18];
    const float* sr_b = (const float*)d_in[19];
    const float* g1   = (const float*)d_in[20];
    const float* g2   = (const float*)d_in[21];
    float* out = (float*)d_out;

    float *prk, *pik, *prr, *pir;
    cudaGetSymbolAddress((void**)&prk, g_rk);
    cudaGetSymbolAddress((void**)&pik, g_ik);
    cudaGetSymbolAddress((void**)&prr, g_rr);
    cudaGetSymbolAddress((void**)&pir, g_ir);

    cudaFuncSetAttribute(attn_k, cudaFuncAttributeMaxDynamicSharedMemorySize,
                         (int)ATT_SMEM);

    // repack weights: offsets in floats
    WPack wp = {};
    wp.w[0] = q_w;  wp.cin[0] = 128; wp.off[0] = 0;
    wp.w[1] = rk_w; wp.cin[1] = 64;  wp.off[1] = 73728;
    wp.w[2] = rv_w; wp.cin[2] = 64;  wp.off[2] = 110592;
    wp.w[3] = ik_w; wp.cin[3] = 64;  wp.off[3] = 147456;
    wp.w[4] = iv_w; wp.cin[4] = 64;  wp.off[4] = 184320;
    wp.w[5] = sr_w; wp.cin[5] = 128; wp.off[5] = 221184;
    wrep_k<<<dim3(288, 1, 6), 256>>>(wp);

    // producers (16 oc/block): Q->K split, rk/ik fp32, rv/iv V fp16
    CPack pp = {};
    pp.c[0] = { x, y,       q_s,  q_b,  nullptr, 128, 1, 0, 0 };
    pp.c[1] = { x, nullptr, rk_s, rk_b, prk,      64, 0, 0, 73728 };
    pp.c[2] = { x, nullptr, rv_s, rv_b, nullptr,  64, 2, 0, 110592 };
    pp.c[3] = { y, nullptr, ik_s, ik_b, pik,      64, 0, 0, 147456 };
    pp.c[4] = { y, nullptr, iv_s, iv_b, nullptr,  64, 2, 1, 184320 };
    conv_k<16><<<dim3(2, 4, 80), 256>>>(pp);

    attn_k<<<dim3(32, 4, 2), 256, ATT_SMEM>>>(x, y, g1, g2);

    // final conv (4 oc/block -> 512 blocks for occupancy)
    CPack ps = {};
    ps.c[0] = { prr, pir, sr_s, sr_b, out, 128, 0, 0, 221184 };
    conv_k<4><<<dim3(2, 4, 64), 256>>>(ps);
}

// round 15
// speedup vs baseline: 1.1185x; 1.0902x over previous
#include <cuda_runtime.h>
#include <cuda_fp16.h>
#include <cstdint>
#include <cstddef>

typedef unsigned long long ull;
typedef uint32_t u32;

#define BN 4
#define CH 64
#define NPIX 4096

// ---------- scratch ----------
__device__ float g_rk[BN*CH*NPIX];
__device__ float g_ik[BN*CH*NPIX];
__device__ float g_rr[BN*CH*NPIX];
__device__ float g_ir[BN*CH*NPIX];
// split-fp16 operands (u32 = f16x2), pitch 36 u32 (72 f16)
__device__ u32 g_Khi[4*4096*36];
__device__ u32 g_Klo[4*4096*36];
__device__ u32 g_Vhi[8*4096*36];
// repacked weights [conv][ci][k][oc64]
__device__ float g_Wp[294912];

// ---------- helpers ----------
__device__ __forceinline__ ull pk2(float a, float b) {
    ull r; asm("mov.b64 %0, {%1, %2};" : "=l"(r) : "f"(a), "f"(b)); return r;
}
__device__ __forceinline__ float2 up2(ull v) {
    float2 f; asm("mov.b64 {%0, %1}, %2;" : "=f"(f.x), "=f"(f.y) : "l"(v)); return f;
}
__device__ __forceinline__ void fma2(ull& d, ull a, ull b) {
    asm("fma.rn.f32x2 %0, %1, %2, %0;" : "+l"(d) : "l"(a), "l"(b));
}
__device__ __forceinline__ u32 s2u(const void* p) {
    u32 a; asm("{ .reg .u64 t; cvta.to.shared.u64 t, %1; cvt.u32.u64 %0, t; }" : "=r"(a) : "l"(p));
    return a;
}
__device__ __forceinline__ u32 pkh2(float lo, float hi) {   // f16x2 {x=lo, y=hi}
    __half2 h = __floats2half2_rn(lo, hi);
    return *(u32*)&h;
}
__device__ __forceinline__ float2 uph2(u32 v) {
    __half2 h = *(__half2*)&v;
    return __half22float2(h);
}
__device__ __forceinline__ void ldsm4(u32& r0, u32& r1, u32& r2, u32& r3, u32 addr) {
    asm volatile("ldmatrix.sync.aligned.m8n8.x4.shared.b16 {%0,%1,%2,%3}, [%4];"
                 : "=r"(r0), "=r"(r1), "=r"(r2), "=r"(r3) : "r"(addr));
}

// ============================================================
// weight repack: w[oc][ci][3x3] -> g_Wp[off + (ci*9+k)*64 + oc]
// ============================================================
struct WPack { const float* w[6]; int cin[6]; int off[6]; };
__global__ void __launch_bounds__(256) wrep_k(WPack W) {
    const int cv = blockIdx.z;
    const int elems = W.cin[cv] * 576;
    const float* src = W.w[cv];
    float* dst = g_Wp + W.off[cv];
    for (int i = blockIdx.x * 256 + threadIdx.x; i < elems; i += 288 * 256) {
        int oc = i & 63, t = i >> 6;
        int k = t % 9, ci = t / 9;
        dst[i] = src[(oc * W.cin[cv] + ci) * 9 + k];
    }
}

// ============================================================
// conv3x3+BN+ReLU: 32x16 px tile, 2 px/thread, OCB oc/block,
// 4 ci/stage, all 16B cp.async, repacked weights.
// mode 0: fp32 out. mode 1: split-fp16 K. mode 2: fp16 V.
// ============================================================
struct CArg { const float* inA; const float* inB;
              const float* s; const float* bb; float* out;
              int cin; int mode; int av; int woff; };
struct CPack { CArg c[5]; };

template<int OCB>
__global__ void __launch_bounds__(256) conv_k(CPack P) {
    constexpr int GR = 64 / OCB;
    constexpr int NWV = 9 * OCB;
    constexpr int PV = 9 * OCB / 4;
    __shared__ __align__(16) float tile[2][4][720];   // 18 x 40
    __shared__ __align__(16) float wsm[2][4][9 * OCB];
    const int tid = threadIdx.x;
    const int tx = tid & 15, ty = tid >> 4;
    const int z = blockIdx.z;
    const CArg a = P.c[z / (4 * GR)];
    const int b   = (z / GR) & 3;
    const int ocb = (z % GR) * OCB;
    const int ox0 = blockIdx.x << 5, oy0 = blockIdx.y << 4;
    const int oy = oy0 + ty;
    const int S = a.cin >> 2;
    const bool wide = (a.cin == 128);

    const float* baseA = a.inA + (size_t)b * 64 * 4096;
    const float* baseB = wide ? a.inB + (size_t)b * 64 * 4096 : baseA;
    const float* wbase = g_Wp + a.woff;

    // ---- hoist tile-load slots ----
    u32 t_sa[3], t_go[3], t_ok[3]; int t_pl[3];
#pragma unroll
    for (int s = 0; s < 3; s++) {
        int i = tid + s * 256;
        if (i >= 720) i = 0;
        int pl = i / 180, r2 = i - pl * 180;
        int r = r2 / 10, v = r2 - r * 10;
        int iy = oy0 - 1 + r, x0 = ox0 - 4 + 4 * v;
        bool ib = iy >= 0 && iy < 64 && x0 >= 0 && x0 <= 60;
        t_pl[s] = pl;
        t_ok[s] = ib ? 16u : 0u;
        t_go[s] = ib ? (u32)(iy * 64 + x0) : 0u;
        t_sa[s] = s2u(&tile[0][pl][r * 40 + 4 * v]);
    }
    // ---- hoist weight slot ----
    const bool wact = tid < NWV;
    u32 w_go = 0, w_sa = 0;
    {
        int j = wact ? tid : 0;
        int pl = j / PV, rem = j - pl * PV;
        int k = rem / (OCB / 4), q = rem - k * (OCB / 4);
        w_go = (u32)(pl * 576 + k * 64 + ocb + 4 * q);
        w_sa = s2u(&wsm[0][pl][k * OCB + 4 * q]);
    }

    ull acc0[OCB / 2], acc1[OCB / 2];
#pragma unroll
    for (int p = 0; p < OCB / 2; p++) { acc0[p] = 0ull; acc1[p] = 0ull; }

    for (int st = 0; st <= S; st++) {
        if (st < S) {
            const int c0 = st * 4;
            const u32 tadd = (st & 1) ? 11520u : 0u;
            const u32 wadd = (st & 1) ? (u32)(144 * OCB) : 0u;
#pragma unroll
            for (int s = 0; s < 3; s++) {
                if (s == 2 && tid >= 208) break;
                int ci = c0 + t_pl[s];
                const float* gp = ((wide && ci >= 64) ? baseB : baseA)
                                  + (ci & 63) * 4096 + t_go[s];
                asm volatile("cp.async.ca.shared.global [%0], [%1], 16, %2;"
                             :: "r"(t_sa[s] + tadd), "l"(gp), "r"(t_ok[s]));
            }
            if (wact) {
                const float* gp = wbase + w_go + c0 * 576;
                asm volatile("cp.async.ca.shared.global [%0], [%1], 16;"
                             :: "r"(w_sa + wadd), "l"(gp));
            }
            asm volatile("cp.async.commit_group;" ::: "memory");
        }
        if (st == 0) continue;
        if (st < S) asm volatile("cp.async.wait_group 1;" ::: "memory");
        else        asm volatile("cp.async.wait_group 0;" ::: "memory");
        __syncthreads();
        const int sb = (st - 1) & 1;
#pragma unroll
        for (int pl = 0; pl < 4; pl++) {
            float v0[9], v1[9];
#pragma unroll
            for (int ky = 0; ky < 3; ky++)
#pragma unroll
                for (int kx = 0; kx < 3; kx++) {
                    int idx = (ty + ky) * 40 + tx + kx + 3;
                    v0[ky * 3 + kx] = tile[sb][pl][idx];
                    v1[ky * 3 + kx] = tile[sb][pl][idx + 16];
                }
#pragma unroll
            for (int k = 0; k < 9; k++) {
                ull vv0 = pk2(v0[k], v0[k]);
                ull vv1 = pk2(v1[k], v1[k]);
#pragma unroll
                for (int q = 0; q < OCB / 4; q++) {
                    ulonglong2 w2 = *(const ulonglong2*)(&wsm[sb][pl][k * OCB + 4 * q]);
                    fma2(acc0[2 * q],     vv0, w2.x);
                    fma2(acc0[2 * q + 1], vv0, w2.y);
                    fma2(acc1[2 * q],     vv1, w2.x);
                    fma2(acc1[2 * q + 1], vv1, w2.y);
                }
            }
        }
        __syncthreads();
    }

    float vals[2][OCB];
#pragma unroll
    for (int p = 0; p < OCB / 2; p++) {
        float2 o0 = up2(acc0[p]), o1 = up2(acc1[p]);
        float s0 = a.s[ocb + 2*p], s1 = a.s[ocb + 2*p + 1];
        float b0 = a.bb[ocb + 2*p], b1 = a.bb[ocb + 2*p + 1];
        vals[0][2*p]   = fmaxf(o0.x * s0 + b0, 0.f);
        vals[0][2*p+1] = fmaxf(o0.y * s1 + b1, 0.f);
        vals[1][2*p]   = fmaxf(o1.x * s0 + b0, 0.f);
        vals[1][2*p+1] = fmaxf(o1.y * s1 + b1, 0.f);
    }
#pragma unroll
    for (int px = 0; px < 2; px++) {
        const int ox = ox0 + tx + px * 16;
        if (a.mode == 0) {
#pragma unroll
            for (int j = 0; j < OCB; j++)
                a.out[(((size_t)b * 64 + ocb + j) * 64 + oy) * 64 + ox] = vals[px][j];
        } else if (a.mode == 1) {
            // K: [b][n][cp], pair over c, fp16 hi/lo
            const size_t nbase = ((size_t)b * 4096 + oy * 64 + ox) * 36 + (ocb >> 1);
#pragma unroll
            for (int p = 0; p < OCB / 2; p++) {
                u32 h = pkh2(vals[px][2*p], vals[px][2*p+1]);
                float2 hf = uph2(h);
                u32 l = pkh2(vals[px][2*p] - hf.x, vals[px][2*p+1] - hf.y);
                g_Khi[nbase + p] = h;
                g_Klo[nbase + p] = l;
            }
        } else {
            // V: [av*4+b][nt=oy][c][np], pair over n, fp16
            const int lane = tid & 31;
            const int np = ox >> 1;
#pragma unroll
            for (int j = 0; j < OCB; j++) {
                float v = vals[px][j];
                float vp = __shfl_xor_sync(0xffffffffu, v, 1);
                if (!(lane & 1)) {
                    size_t idx = (((size_t)(a.av * 4 + b) * 64 + oy) * 64 + ocb + j) * 36 + np;
                    g_Vhi[idx] = pkh2(v, vp);
                }
            }
        }
    }
}

// ============================================================
// flash attention: warp mma fp16, S 3-term split / PV 1-term,
// ldmatrix.x4, m-tile 128, 256 thr, online softmax (P<=1,
// fp16-safe), 3-stage pipeline. grid (32, 4, 2)
// ============================================================
#define MMA(d, a, b0_, b1_) \
    asm volatile("mma.sync.aligned.m16n8k16.row.col.f32.f16.f16.f32 " \
        "{%0,%1,%2,%3}, {%4,%5,%6,%7}, {%8,%9}, {%0,%1,%2,%3};" \
        : "+f"((d)[0]), "+f"((d)[1]), "+f"((d)[2]), "+f"((d)[3]) \
        : "r"((a)[0]), "r"((a)[1]), "r"((a)[2]), "r"((a)[3]), "r"(b0_), "r"(b1_))

#define STG_BYTES 27648u     // KH 9216 | KL 9216 | VH 9216
#define ATT_SMEM 82944u      // 3 buffers; Q staged over buf1/2

__device__ __forceinline__ void fetch_chunk(u32 sbase, int tid, int nt,
        const u32* kh, const u32* kl, const u32* vh) {
    const u32 off = (u32)nt * 2304u;
#pragma unroll
    for (int k = 0; k < 7; k++) {
        int idx = tid + k * 256;          // 0..1727
        if (k == 6 && idx >= 1728) break;
        int r = idx / 576, l = idx - r * 576;
        const u32* gp = (r == 0 ? kh : r == 1 ? kl : vh) + off + l * 4;
        asm volatile("cp.async.cg.shared.global [%0], [%1], 16;"
                     :: "r"(sbase + r * 9216u + l * 16u), "l"(gp));
    }
    asm volatile("cp.async.commit_group;" ::: "memory");
}

__global__ void __launch_bounds__(256) attn_k(const float* __restrict__ x,
                                              const float* __restrict__ y,
                                              const float* __restrict__ g1,
                                              const float* __restrict__ g2) {
    extern __shared__ char smc[];
    float* Qs = (float*)(smc + STG_BYTES);   // overlays buf1/2
    const u32 sbA = s2u(smc);
    const int tid = threadIdx.x;
    const int w = tid >> 5, lane = tid & 31;
    const int qr = lane >> 2, qc2 = (lane & 3) * 2;
    const int m0 = blockIdx.x * 128, b = blockIdx.y, a = blockIdx.z;

    // ldmatrix per-lane offset
    const u32 lmOff = (((lane >> 4) & 1) * 8 + (lane & 7)) * 144u
                    + ((lane >> 3) & 1) * 16u;

    const size_t boff = (size_t)b * CH * NPIX;
    const float* Aq  = (a ? g_ik : g_rk) + boff;
    const float* res = (a ? x : y) + boff;
    float* outp      = (a ? g_ir : g_rr) + boff;
    const float gamma = a ? g2[0] : g1[0];
    const u32* kh = g_Khi + (size_t)b * 147456;
    const u32* kl = g_Klo + (size_t)b * 147456;
    const u32* vh = g_Vhi + (size_t)(a * 4 + b) * 147456;

    // fetch chunk0 -> buf0; stage Q [m][c] fp32 over buf1/2
    fetch_chunk(sbA, tid, 0, kh, kl, vh);
    for (int i = tid; i < 8192; i += 256) {
        int m = i & 127, c = i >> 7;
        Qs[m * 68 + c] = Aq[(size_t)c * NPIX + m0 + m];
    }
    __syncthreads();

    // Q fragments hi/lo fp16 (row-major A)
    u32 ah[4][4], al[4][4];
    const int r0 = w * 16 + qr;
#pragma unroll
    for (int j = 0; j < 4; j++) {
        int c0 = j * 16 + qc2;
        float2 fs[4] = { *(float2*)(Qs + r0 * 68 + c0),
                         *(float2*)(Qs + (r0 + 8) * 68 + c0),
                         *(float2*)(Qs + r0 * 68 + c0 + 8),
                         *(float2*)(Qs + (r0 + 8) * 68 + c0 + 8) };
#pragma unroll
        for (int r = 0; r < 4; r++) {
            u32 h = pkh2(fs[r].x, fs[r].y);
            float2 hf = uph2(h);
            ah[j][r] = h;
            al[j][r] = pkh2(fs[r].x - hf.x, fs[r].y - hf.y);
        }
    }
    __syncthreads();   // all Q reads done before buf1/2 prefetches
    fetch_chunk(sbA + STG_BYTES, tid, 1, kh, kl, vh);
    fetch_chunk(sbA + 2 * STG_BYTES, tid, 2, kh, kl, vh);

    float O[8][4];
#pragma unroll
    for (int f = 0; f < 8; f++)
#pragma unroll
        for (int r = 0; r < 4; r++) O[f][r] = 0.f;
    float M0 = -1e30f, M1 = -1e30f, L0 = 0.f, L1 = 0.f;

    for (int nt = 0; nt < 64; nt++) {
        if (nt < 62)      asm volatile("cp.async.wait_group 2;" ::: "memory");
        else if (nt == 62) asm volatile("cp.async.wait_group 1;" ::: "memory");
        else              asm volatile("cp.async.wait_group 0;" ::: "memory");
        __syncthreads();
        const u32 sbufU = sbA + (u32)(nt % 3) * STG_BYTES;
        const u32 sK = sbufU + lmOff;            // K hi (lo at +9216)
        const u32 sV = sbufU + 18432u + lmOff;   // V

        // ---- S = Q K^T, 3-term fp16 split ----
        float S[8][4];
#pragma unroll
        for (int f = 0; f < 8; f++)
#pragma unroll
            for (int r = 0; r < 4; r++) S[f][r] = 0.f;
#pragma unroll
        for (int j = 0; j < 4; j++) {
#pragma unroll
            for (int f2 = 0; f2 < 4; f2++) {
                u32 h0, h1, h2, h3, l0, l1, l2, l3;
                ldsm4(h0, h1, h2, h3, sK + f2 * 2304u + j * 32u);
                ldsm4(l0, l1, l2, l3, sK + 9216u + f2 * 2304u + j * 32u);
                MMA(S[2*f2],   ah[j], h0, h1);
                MMA(S[2*f2],   al[j], h0, h1);
                MMA(S[2*f2],   ah[j], l0, l1);
                MMA(S[2*f2+1], ah[j], h2, h3);
                MMA(S[2*f2+1], al[j], h2, h3);
                MMA(S[2*f2+1], ah[j], l2, l3);
            }
        }

        // ---- online softmax (P <= 1 always; fp16-safe) ----
        {
            float mx0 = -1e30f, mx1 = -1e30f;
#pragma unroll
            for (int f = 0; f < 8; f++) {
                mx0 = fmaxf(mx0, fmaxf(S[f][0], S[f][1]));
                mx1 = fmaxf(mx1, fmaxf(S[f][2], S[f][3]));
            }
            mx0 = fmaxf(mx0, __shfl_xor_sync(0xffffffffu, mx0, 1));
            mx0 = fmaxf(mx0, __shfl_xor_sync(0xffffffffu, mx0, 2));
            mx1 = fmaxf(mx1, __shfl_xor_sync(0xffffffffu, mx1, 1));
            mx1 = fmaxf(mx1, __shfl_xor_sync(0xffffffffu, mx1, 2));
            float mn0 = fmaxf(M0, mx0), mn1 = fmaxf(M1, mx1);
            float sc0 = __expf(M0 - mn0), sc1 = __expf(M1 - mn1);
            M0 = mn0; M1 = mn1;
            L0 *= sc0; L1 *= sc1;
#pragma unroll
            for (int f = 0; f < 8; f++) {
                O[f][0] *= sc0; O[f][1] *= sc0;
                O[f][2] *= sc1; O[f][3] *= sc1;
            }
        }
#pragma unroll
        for (int f = 0; f < 8; f++) {
            S[f][0] = __expf(S[f][0] - M0); S[f][1] = __expf(S[f][1] - M0);
            S[f][2] = __expf(S[f][2] - M1); S[f][3] = __expf(S[f][3] - M1);
            L0 += S[f][0] + S[f][1];
            L1 += S[f][2] + S[f][3];
        }

        // ---- O += P V^T (1-term fp16, P in [0,1]) ----
#pragma unroll
        for (int j2 = 0; j2 < 4; j2++) {
            u32 ph[4];
            ph[0] = pkh2(S[2*j2][0],   S[2*j2][1]);
            ph[1] = pkh2(S[2*j2][2],   S[2*j2][3]);
            ph[2] = pkh2(S[2*j2+1][0], S[2*j2+1][1]);
            ph[3] = pkh2(S[2*j2+1][2], S[2*j2+1][3]);
#pragma unroll
            for (int q = 0; q < 4; q++) {
                u32 v0, v1, v2, v3;
                ldsm4(v0, v1, v2, v3, sV + q * 2304u + j2 * 32u);
                MMA(O[2*q],   ph, v0, v1);
                MMA(O[2*q+1], ph, v2, v3);
            }
        }
        __syncthreads();
        if (nt + 3 < 64)
            fetch_chunk(sbA + (u32)(nt % 3) * STG_BYTES, tid, nt + 3, kh, kl, vh);
    }

    // ---- final L reduction (quad) + epilogue ----
    L0 += __shfl_xor_sync(0xffffffffu, L0, 1);
    L0 += __shfl_xor_sync(0xffffffffu, L0, 2);
    L1 += __shfl_xor_sync(0xffffffffu, L1, 1);
    L1 += __shfl_xor_sync(0xffffffffu, L1, 2);
    float i0 = 1.0f / L0, i1 = 1.0f / L1;
    const int mA = m0 + r0, mB = mA + 8;
#pragma unroll
    for (int fc = 0; fc < 8; fc++) {
        int c0 = fc * 8 + qc2;
        size_t iA0 = (size_t)c0 * NPIX + mA;
        size_t iA1 = (size_t)(c0 + 1) * NPIX + mA;
        outp[iA0] = gamma * (O[fc][0] * i0) + res[iA0];
        outp[iA1] = gamma * (O[fc][1] * i0) + res[iA1];
        size_t iB0 = (size_t)c0 * NPIX + mB;
        size_t iB1 = (size_t)(c0 + 1) * NPIX + mB;
        outp[iB0] = gamma * (O[fc][2] * i1) + res[iB0];
        outp[iB1] = gamma * (O[fc][3] * i1) + res[iB1];
    }
}

// ============================================================
extern "C" void kernel_launch(void* const* d_in, const int* in_sizes, int n_in,
                              void* d_out, int out_size) {
    const float* x    = (const float*)d_in[0];
    const float* y    = (const float*)d_in[1];
    const float* q_w  = (const float*)d_in[2];
    const float* q_s  = (const float*)d_in[3];
    const float* q_b  = (const float*)d_in[4];
    const float* rk_w = (const float*)d_in[5];
    const float* rk_s = (const float*)d_in[6];
    const float* rk_b = (const float*)d_in[7];
    const float* rv_w = (const float*)d_in[8];
    const float* rv_s = (const float*)d_in[9];
    const float* rv_b = (const float*)d_in[10];
    const float* ik_w = (const float*)d_in[11];
    const float* ik_s = (const float*)d_in[12];
    const float* ik_b = (const float*)d_in[13];
    const float* iv_w = (const float*)d_in[14];
    const float* iv_s = (const float*)d_in[15];
    const float* iv_b = (const float*)d_in[16];
    const float* sr_w = (const float*)d_in[17];
    const float* sr_s = (const float*)d_in[18];
    const float* sr_b = (const float*)d_in[19];
    const float* g1   = (const float*)d_in[20];
    const float* g2   = (const float*)d_in[21];
    float* out = (float*)d_out;

    float *prk, *pik, *prr, *pir;
    cudaGetSymbolAddress((void**)&prk, g_rk);
    cudaGetSymbolAddress((void**)&pik, g_ik);
    cudaGetSymbolAddress((void**)&prr, g_rr);
    cudaGetSymbolAddress((void**)&pir, g_ir);

    cudaFuncSetAttribute(attn_k, cudaFuncAttributeMaxDynamicSharedMemorySize,
                         (int)ATT_SMEM);

    // repack weights: offsets in floats
    WPack wp = {};
    wp.w[0] = q_w;  wp.cin[0] = 128; wp.off[0] = 0;
    wp.w[1] = rk_w; wp.cin[1] = 64;  wp.off[1] = 73728;
    wp.w[2] = rv_w; wp.cin[2] = 64;  wp.off[2] = 110592;
    wp.w[3] = ik_w; wp.cin[3] = 64;  wp.off[3] = 147456;
    wp.w[4] = iv_w; wp.cin[4] = 64;  wp.off[4] = 184320;
    wp.w[5] = sr_w; wp.cin[5] = 128; wp.off[5] = 221184;
    wrep_k<<<dim3(288, 1, 6), 256>>>(wp);

    // producers (16 oc/block): Q->K split, rk/ik fp32, rv/iv V fp16
    CPack pp = {};
    pp.c[0] = { x, y,       q_s,  q_b,  nullptr, 128, 1, 0, 0 };
    pp.c[1] = { x, nullptr, rk_s, rk_b, prk,      64, 0, 0, 73728 };
    pp.c[2] = { x, nullptr, rv_s, rv_b, nullptr,  64, 2, 0, 110592 };
    pp.c[3] = { y, nullptr, ik_s, ik_b, pik,      64, 0, 0, 147456 };
    pp.c[4] = { y, nullptr, iv_s, iv_b, nullptr,  64, 2, 1, 184320 };
    conv_k<16><<<dim3(2, 4, 80), 256>>>(pp);

    attn_k<<<dim3(32, 4, 2), 256, ATT_SMEM>>>(x, y, g1, g2);

    // final conv (8 oc/block, grid 256 — measured-best config)
    CPack ps = {};
    ps.c[0] = { prr, pir, sr_s, sr_b, out, 128, 0, 0, 221184 };
    conv_k<8><<<dim3(2, 4, 32), 256>>>(ps);
}

// round 16
// speedup vs baseline: 1.2264x; 1.0965x over previous
#include <cuda_runtime.h>
#include <cuda_fp16.h>
#include <cstdint>
#include <cstddef>

typedef unsigned long long ull;
typedef uint32_t u32;

#define BN 4
#define CH 64
#define NPIX 4096

// ---------- scratch ----------
__device__ float g_rk[BN*CH*NPIX];
__device__ float g_ik[BN*CH*NPIX];
__device__ float g_rr[BN*CH*NPIX];
__device__ float g_ir[BN*CH*NPIX];
// fp16 operands (u32 = f16x2), pitch 36 u32 (72 f16)
__device__ u32 g_Khi[4*4096*36];     // K full fp16 [b][n][cp]
__device__ u32 g_Qlo[4*4096*36];     // (unused; kept for layout stability) 
__device__ u32 g_Vhi[8*4096*36];     // V fp16 [av*4+b][nt][c][np]
// repacked weights [conv][ci][k][oc64]
__device__ float g_Wp[294912];

// ---------- helpers ----------
__device__ __forceinline__ ull pk2(float a, float b) {
    ull r; asm("mov.b64 %0, {%1, %2};" : "=l"(r) : "f"(a), "f"(b)); return r;
}
__device__ __forceinline__ float2 up2(ull v) {
    float2 f; asm("mov.b64 {%0, %1}, %2;" : "=f"(f.x), "=f"(f.y) : "l"(v)); return f;
}
__device__ __forceinline__ void fma2(ull& d, ull a, ull b) {
    asm("fma.rn.f32x2 %0, %1, %2, %0;" : "+l"(d) : "l"(a), "l"(b));
}
__device__ __forceinline__ u32 s2u(const void* p) {
    u32 a; asm("{ .reg .u64 t; cvta.to.shared.u64 t, %1; cvt.u32.u64 %0, t; }" : "=r"(a) : "l"(p));
    return a;
}
__device__ __forceinline__ u32 pkh2(float lo, float hi) {   // f16x2 {x=lo, y=hi}
    __half2 h = __floats2half2_rn(lo, hi);
    return *(u32*)&h;
}
__device__ __forceinline__ float2 uph2(u32 v) {
    __half2 h = *(__half2*)&v;
    return __half22float2(h);
}
__device__ __forceinline__ u32 h2ex2(u32 x) {
    u32 r; asm("ex2.approx.f16x2 %0, %1;" : "=r"(r) : "r"(x)); return r;
}
__device__ __forceinline__ void ldsm4(u32& r0, u32& r1, u32& r2, u32& r3, u32 addr) {
    asm volatile("ldmatrix.sync.aligned.m8n8.x4.shared.b16 {%0,%1,%2,%3}, [%4];"
                 : "=r"(r0), "=r"(r1), "=r"(r2), "=r"(r3) : "r"(addr));
}

// ============================================================
// weight repack: w[oc][ci][3x3] -> g_Wp[off + (ci*9+k)*64 + oc]
// ============================================================
struct WPack { const float* w[6]; int cin[6]; int off[6]; };
__global__ void __launch_bounds__(256) wrep_k(WPack W) {
    const int cv = blockIdx.z;
    const int elems = W.cin[cv] * 576;
    const float* src = W.w[cv];
    float* dst = g_Wp + W.off[cv];
    for (int i = blockIdx.x * 256 + threadIdx.x; i < elems; i += 288 * 256) {
        int oc = i & 63, t = i >> 6;
        int k = t % 9, ci = t / 9;
        dst[i] = src[(oc * W.cin[cv] + ci) * 9 + k];
    }
}

// ============================================================
// conv3x3+BN+ReLU: 32x16 px tile, 2 px/thread, OCB oc/block,
// 4 ci/stage, all 16B cp.async, repacked weights.
// mode 0: fp32 out. mode 1: fp16 K. mode 2: fp16 V.
// ============================================================
struct CArg { const float* inA; const float* inB;
              const float* s; const float* bb; float* out;
              int cin; int mode; int av; int woff; };
struct CPack { CArg c[5]; };

template<int OCB>
__global__ void __launch_bounds__(256) conv_k(CPack P) {
    constexpr int GR = 64 / OCB;
    constexpr int NWV = 9 * OCB;
    constexpr int PV = 9 * OCB / 4;
    __shared__ __align__(16) float tile[2][4][720];   // 18 x 40
    __shared__ __align__(16) float wsm[2][4][9 * OCB];
    const int tid = threadIdx.x;
    const int tx = tid & 15, ty = tid >> 4;
    const int z = blockIdx.z;
    const CArg a = P.c[z / (4 * GR)];
    const int b   = (z / GR) & 3;
    const int ocb = (z % GR) * OCB;
    const int ox0 = blockIdx.x << 5, oy0 = blockIdx.y << 4;
    const int oy = oy0 + ty;
    const int S = a.cin >> 2;
    const bool wide = (a.cin == 128);

    const float* baseA = a.inA + (size_t)b * 64 * 4096;
    const float* baseB = wide ? a.inB + (size_t)b * 64 * 4096 : baseA;
    const float* wbase = g_Wp + a.woff;

    // ---- hoist tile-load slots ----
    u32 t_sa[3], t_go[3], t_ok[3]; int t_pl[3];
#pragma unroll
    for (int s = 0; s < 3; s++) {
        int i = tid + s * 256;
        if (i >= 720) i = 0;
        int pl = i / 180, r2 = i - pl * 180;
        int r = r2 / 10, v = r2 - r * 10;
        int iy = oy0 - 1 + r, x0 = ox0 - 4 + 4 * v;
        bool ib = iy >= 0 && iy < 64 && x0 >= 0 && x0 <= 60;
        t_pl[s] = pl;
        t_ok[s] = ib ? 16u : 0u;
        t_go[s] = ib ? (u32)(iy * 64 + x0) : 0u;
        t_sa[s] = s2u(&tile[0][pl][r * 40 + 4 * v]);
    }
    // ---- hoist weight slot ----
    const bool wact = tid < NWV;
    u32 w_go = 0, w_sa = 0;
    {
        int j = wact ? tid : 0;
        int pl = j / PV, rem = j - pl * PV;
        int k = rem / (OCB / 4), q = rem - k * (OCB / 4);
        w_go = (u32)(pl * 576 + k * 64 + ocb + 4 * q);
        w_sa = s2u(&wsm[0][pl][k * OCB + 4 * q]);
    }

    ull acc0[OCB / 2], acc1[OCB / 2];
#pragma unroll
    for (int p = 0; p < OCB / 2; p++) { acc0[p] = 0ull; acc1[p] = 0ull; }

    for (int st = 0; st <= S; st++) {
        if (st < S) {
            const int c0 = st * 4;
            const u32 tadd = (st & 1) ? 11520u : 0u;
            const u32 wadd = (st & 1) ? (u32)(144 * OCB) : 0u;
#pragma unroll
            for (int s = 0; s < 3; s++) {
                if (s == 2 && tid >= 208) break;
                int ci = c0 + t_pl[s];
                const float* gp = ((wide && ci >= 64) ? baseB : baseA)
                                  + (ci & 63) * 4096 + t_go[s];
                asm volatile("cp.async.ca.shared.global [%0], [%1], 16, %2;"
                             :: "r"(t_sa[s] + tadd), "l"(gp), "r"(t_ok[s]));
            }
            if (wact) {
                const float* gp = wbase + w_go + c0 * 576;
                asm volatile("cp.async.ca.shared.global [%0], [%1], 16;"
                             :: "r"(w_sa + wadd), "l"(gp));
            }
            asm volatile("cp.async.commit_group;" ::: "memory");
        }
        if (st == 0) continue;
        if (st < S) asm volatile("cp.async.wait_group 1;" ::: "memory");
        else        asm volatile("cp.async.wait_group 0;" ::: "memory");
        __syncthreads();
        const int sb = (st - 1) & 1;
#pragma unroll
        for (int pl = 0; pl < 4; pl++) {
            float v0[9], v1[9];
#pragma unroll
            for (int ky = 0; ky < 3; ky++)
#pragma unroll
                for (int kx = 0; kx < 3; kx++) {
                    int idx = (ty + ky) * 40 + tx + kx + 3;
                    v0[ky * 3 + kx] = tile[sb][pl][idx];
                    v1[ky * 3 + kx] = tile[sb][pl][idx + 16];
                }
#pragma unroll
            for (int k = 0; k < 9; k++) {
                ull vv0 = pk2(v0[k], v0[k]);
                ull vv1 = pk2(v1[k], v1[k]);
#pragma unroll
                for (int q = 0; q < OCB / 4; q++) {
                    ulonglong2 w2 = *(const ulonglong2*)(&wsm[sb][pl][k * OCB + 4 * q]);
                    fma2(acc0[2 * q],     vv0, w2.x);
                    fma2(acc0[2 * q + 1], vv0, w2.y);
                    fma2(acc1[2 * q],     vv1, w2.x);
                    fma2(acc1[2 * q + 1], vv1, w2.y);
                }
            }
        }
        __syncthreads();
    }

    float vals[2][OCB];
#pragma unroll
    for (int p = 0; p < OCB / 2; p++) {
        float2 o0 = up2(acc0[p]), o1 = up2(acc1[p]);
        float s0 = a.s[ocb + 2*p], s1 = a.s[ocb + 2*p + 1];
        float b0 = a.bb[ocb + 2*p], b1 = a.bb[ocb + 2*p + 1];
        vals[0][2*p]   = fmaxf(o0.x * s0 + b0, 0.f);
        vals[0][2*p+1] = fmaxf(o0.y * s1 + b1, 0.f);
        vals[1][2*p]   = fmaxf(o1.x * s0 + b0, 0.f);
        vals[1][2*p+1] = fmaxf(o1.y * s1 + b1, 0.f);
    }
#pragma unroll
    for (int px = 0; px < 2; px++) {
        const int ox = ox0 + tx + px * 16;
        if (a.mode == 0) {
#pragma unroll
            for (int j = 0; j < OCB; j++)
                a.out[(((size_t)b * 64 + ocb + j) * 64 + oy) * 64 + ox] = vals[px][j];
        } else if (a.mode == 1) {
            // K: [b][n][cp], pair over c, plain fp16
            const size_t nbase = ((size_t)b * 4096 + oy * 64 + ox) * 36 + (ocb >> 1);
#pragma unroll
            for (int p = 0; p < OCB / 2; p++)
                g_Khi[nbase + p] = pkh2(vals[px][2*p], vals[px][2*p+1]);
        } else {
            // V: [av*4+b][nt=oy][c][np], pair over n, fp16
            const int lane = tid & 31;
            const int np = ox >> 1;
#pragma unroll
            for (int j = 0; j < OCB; j++) {
                float v = vals[px][j];
                float vp = __shfl_xor_sync(0xffffffffu, v, 1);
                if (!(lane & 1)) {
                    size_t idx = (((size_t)(a.av * 4 + b) * 64 + oy) * 64 + ocb + j) * 36 + np;
                    g_Vhi[idx] = pkh2(v, vp);
                }
            }
        }
    }
}

// ============================================================
// flash attention: warp mma fp16, S 2-term (Q split, K fp16) /
// PV 1-term, fp16x2 exp, ldmatrix.x4, m-tile 128, 256 thr,
// online softmax, 3-stage pipeline. grid (32, 4, 2)
// ============================================================
#define MMA(d, a, b0_, b1_) \
    asm volatile("mma.sync.aligned.m16n8k16.row.col.f32.f16.f16.f32 " \
        "{%0,%1,%2,%3}, {%4,%5,%6,%7}, {%8,%9}, {%0,%1,%2,%3};" \
        : "+f"((d)[0]), "+f"((d)[1]), "+f"((d)[2]), "+f"((d)[3]) \
        : "r"((a)[0]), "r"((a)[1]), "r"((a)[2]), "r"((a)[3]), "r"(b0_), "r"(b1_))

#define STG_BYTES 18432u     // KH 9216 | VH 9216
#define ATT_SMEM 55296u      // 3 buffers; Q staged over buf1/2

__device__ __forceinline__ void fetch_chunk(u32 sbase, int tid, int nt,
        const u32* kh, const u32* vh) {
    const u32 off = (u32)nt * 2304u;
#pragma unroll
    for (int k = 0; k < 5; k++) {
        int idx = tid + k * 256;          // 0..1151
        if (k == 4 && idx >= 1152) break;
        int r = idx / 576, l = idx - r * 576;
        const u32* gp = (r == 0 ? kh : vh) + off + l * 4;
        asm volatile("cp.async.cg.shared.global [%0], [%1], 16;"
                     :: "r"(sbase + r * 9216u + l * 16u), "l"(gp));
    }
    asm volatile("cp.async.commit_group;" ::: "memory");
}

__global__ void __launch_bounds__(256) attn_k(const float* __restrict__ x,
                                              const float* __restrict__ y,
                                              const float* __restrict__ g1,
                                              const float* __restrict__ g2) {
    extern __shared__ char smc[];
    float* Qs = (float*)(smc + STG_BYTES);   // overlays buf1/2 (34816 <= 36864)
    const u32 sbA = s2u(smc);
    const int tid = threadIdx.x;
    const int w = tid >> 5, lane = tid & 31;
    const int qr = lane >> 2, qc2 = (lane & 3) * 2;
    const int m0 = blockIdx.x * 128, b = blockIdx.y, a = blockIdx.z;
    const float LOG2E = 1.4426950408889634f;

    // ldmatrix per-lane offset
    const u32 lmOff = (((lane >> 4) & 1) * 8 + (lane & 7)) * 144u
                    + ((lane >> 3) & 1) * 16u;

    const size_t boff = (size_t)b * CH * NPIX;
    const float* Aq  = (a ? g_ik : g_rk) + boff;
    const float* res = (a ? x : y) + boff;
    float* outp      = (a ? g_ir : g_rr) + boff;
    const float gamma = a ? g2[0] : g1[0];
    const u32* kh = g_Khi + (size_t)b * 147456;
    const u32* vh = g_Vhi + (size_t)(a * 4 + b) * 147456;

    // fetch chunk0 -> buf0; stage Q [m][c] fp32 over buf1/2
    fetch_chunk(sbA, tid, 0, kh, vh);
    for (int i = tid; i < 8192; i += 256) {
        int m = i & 127, c = i >> 7;
        Qs[m * 68 + c] = Aq[(size_t)c * NPIX + m0 + m];
    }
    __syncthreads();

    // Q fragments hi/lo fp16 (row-major A)
    u32 ah[4][4], al[4][4];
    const int r0 = w * 16 + qr;
#pragma unroll
    for (int j = 0; j < 4; j++) {
        int c0 = j * 16 + qc2;
        float2 fs[4] = { *(float2*)(Qs + r0 * 68 + c0),
                         *(float2*)(Qs + (r0 + 8) * 68 + c0),
                         *(float2*)(Qs + r0 * 68 + c0 + 8),
                         *(float2*)(Qs + (r0 + 8) * 68 + c0 + 8) };
#pragma unroll
        for (int r = 0; r < 4; r++) {
            u32 h = pkh2(fs[r].x, fs[r].y);
            float2 hf = uph2(h);
            ah[j][r] = h;
            al[j][r] = pkh2(fs[r].x - hf.x, fs[r].y - hf.y);
        }
    }
    __syncthreads();   // all Q reads done before buf1/2 prefetches
    fetch_chunk(sbA + STG_BYTES, tid, 1, kh, vh);
    fetch_chunk(sbA + 2 * STG_BYTES, tid, 2, kh, vh);

    float O[8][4];
#pragma unroll
    for (int f = 0; f < 8; f++)
#pragma unroll
        for (int r = 0; r < 4; r++) O[f][r] = 0.f;
    float M0 = -1e30f, M1 = -1e30f, L0 = 0.f, L1 = 0.f;

    for (int nt = 0; nt < 64; nt++) {
        if (nt < 62)      asm volatile("cp.async.wait_group 2;" ::: "memory");
        else if (nt == 62) asm volatile("cp.async.wait_group 1;" ::: "memory");
        else              asm volatile("cp.async.wait_group 0;" ::: "memory");
        __syncthreads();
        const u32 sbufU = sbA + (u32)(nt % 3) * STG_BYTES;
        const u32 sK = sbufU + lmOff;           // K fp16
        const u32 sV = sbufU + 9216u + lmOff;   // V fp16

        // ---- S = Q K^T, 2-term (Qh + Ql) x K ----
        float S[8][4];
#pragma unroll
        for (int f = 0; f < 8; f++)
#pragma unroll
            for (int r = 0; r < 4; r++) S[f][r] = 0.f;
#pragma unroll
        for (int j = 0; j < 4; j++) {
#pragma unroll
            for (int f2 = 0; f2 < 4; f2++) {
                u32 h0, h1, h2, h3;
                ldsm4(h0, h1, h2, h3, sK + f2 * 2304u + j * 32u);
                MMA(S[2*f2],   ah[j], h0, h1);
                MMA(S[2*f2],   al[j], h0, h1);
                MMA(S[2*f2+1], ah[j], h2, h3);
                MMA(S[2*f2+1], al[j], h2, h3);
            }
        }

        // ---- online softmax, fp16x2 exp -> P fragments directly ----
        {
            float mx0 = -1e30f, mx1 = -1e30f;
#pragma unroll
            for (int f = 0; f < 8; f++) {
                mx0 = fmaxf(mx0, fmaxf(S[f][0], S[f][1]));
                mx1 = fmaxf(mx1, fmaxf(S[f][2], S[f][3]));
            }
            mx0 = fmaxf(mx0, __shfl_xor_sync(0xffffffffu, mx0, 1));
            mx0 = fmaxf(mx0, __shfl_xor_sync(0xffffffffu, mx0, 2));
            mx1 = fmaxf(mx1, __shfl_xor_sync(0xffffffffu, mx1, 1));
            mx1 = fmaxf(mx1, __shfl_xor_sync(0xffffffffu, mx1, 2));
            float mn0 = fmaxf(M0, mx0), mn1 = fmaxf(M1, mx1);
            float sc0 = __expf(M0 - mn0), sc1 = __expf(M1 - mn1);
            M0 = mn0; M1 = mn1;
            L0 *= sc0; L1 *= sc1;
#pragma unroll
            for (int f = 0; f < 8; f++) {
                O[f][0] *= sc0; O[f][1] *= sc0;
                O[f][2] *= sc1; O[f][3] *= sc1;
            }
        }
        u32 Pf[8][2];
#pragma unroll
        for (int f = 0; f < 8; f++) {
            u32 a0 = pkh2((S[f][0] - M0) * LOG2E, (S[f][1] - M0) * LOG2E);
            u32 a1 = pkh2((S[f][2] - M1) * LOG2E, (S[f][3] - M1) * LOG2E);
            Pf[f][0] = h2ex2(a0);
            Pf[f][1] = h2ex2(a1);
            float2 u = uph2(Pf[f][0]); L0 += u.x + u.y;
            float2 v = uph2(Pf[f][1]); L1 += v.x + v.y;
        }

        // ---- O += P V^T (1-term fp16, P in [0,1]) ----
#pragma unroll
        for (int j2 = 0; j2 < 4; j2++) {
            u32 ph[4];
            ph[0] = Pf[2*j2][0];
            ph[1] = Pf[2*j2][1];
            ph[2] = Pf[2*j2+1][0];
            ph[3] = Pf[2*j2+1][1];
#pragma unroll
            for (int q = 0; q < 4; q++) {
                u32 v0, v1, v2, v3;
                ldsm4(v0, v1, v2, v3, sV + q * 2304u + j2 * 32u);
                MMA(O[2*q],   ph, v0, v1);
                MMA(O[2*q+1], ph, v2, v3);
            }
        }
        __syncthreads();
        if (nt + 3 < 64)
            fetch_chunk(sbA + (u32)(nt % 3) * STG_BYTES, tid, nt + 3, kh, vh);
    }

    // ---- final L reduction (quad) + epilogue ----
    L0 += __shfl_xor_sync(0xffffffffu, L0, 1);
    L0 += __shfl_xor_sync(0xffffffffu, L0, 2);
    L1 += __shfl_xor_sync(0xffffffffu, L1, 1);
    L1 += __shfl_xor_sync(0xffffffffu, L1, 2);
    float i0 = 1.0f / L0, i1 = 1.0f / L1;
    const int mA = m0 + r0, mB = mA + 8;
#pragma unroll
    for (int fc = 0; fc < 8; fc++) {
        int c0 = fc * 8 + qc2;
        size_t iA0 = (size_t)c0 * NPIX + mA;
        size_t iA1 = (size_t)(c0 + 1) * NPIX + mA;
        outp[iA0] = gamma * (O[fc][0] * i0) + res[iA0];
        outp[iA1] = gamma * (O[fc][1] * i0) + res[iA1];
        size_t iB0 = (size_t)c0 * NPIX + mB;
        size_t iB1 = (size_t)(c0 + 1) * NPIX + mB;
        outp[iB0] = gamma * (O[fc][2] * i1) + res[iB0];
        outp[iB1] = gamma * (O[fc][3] * i1) + res[iB1];
    }
}

// ============================================================
extern "C" void kernel_launch(void* const* d_in, const int* in_sizes, int n_in,
                              void* d_out, int out_size) {
    const float* x    = (const float*)d_in[0];
    const float* y    = (const float*)d_in[1];
    const float* q_w  = (const float*)d_in[2];
    const float* q_s  = (const float*)d_in[3];
    const float* q_b  = (const float*)d_in[4];
    const float* rk_w = (const float*)d_in[5];
    const float* rk_s = (const float*)d_in[6];
    const float* rk_b = (const float*)d_in[7];
    const float* rv_w = (const float*)d_in[8];
    const float* rv_s = (const float*)d_in[9];
    const float* rv_b = (const float*)d_in[10];
    const float* ik_w = (const float*)d_in[11];
    const float* ik_s = (const float*)d_in[12];
    const float* ik_b = (const float*)d_in[13];
    const float* iv_w = (const float*)d_in[14];
    const float* iv_s = (const float*)d_in[15];
    const float* iv_b = (const float*)d_in[16];
    const float* sr_w = (const float*)d_in[17];
    const float* sr_s = (const float*)d_in[18];
    const float* sr_b = (const float*)d_in[19];
    const float* g1   = (const float*)d_in[20];
    const float* g2   = (const float*)d_in[21];
    float* out = (float*)d_out;

    float *prk, *pik, *prr, *pir;
    cudaGetSymbolAddress((void**)&prk, g_rk);
    cudaGetSymbolAddress((void**)&pik, g_ik);
    cudaGetSymbolAddress((void**)&prr, g_rr);
    cudaGetSymbolAddress((void**)&pir, g_ir);

    cudaFuncSetAttribute(attn_k, cudaFuncAttributeMaxDynamicSharedMemorySize,
                         (int)ATT_SMEM);

    // repack weights: offsets in floats
    WPack wp = {};
    wp.w[0] = q_w;  wp.cin[0] = 128; wp.off[0] = 0;
    wp.w[1] = rk_w; wp.cin[1] = 64;  wp.off[1] = 73728;
    wp.w[2] = rv_w; wp.cin[2] = 64;  wp.off[2] = 110592;
    wp.w[3] = ik_w; wp.cin[3] = 64;  wp.off[3] = 147456;
    wp.w[4] = iv_w; wp.cin[4] = 64;  wp.off[4] = 184320;
    wp.w[5] = sr_w; wp.cin[5] = 128; wp.off[5] = 221184;
    wrep_k<<<dim3(288, 1, 6), 256>>>(wp);

    // producers (16 oc/block): Q->K fp16, rk/ik fp32, rv/iv V fp16
    CPack pp = {};
    pp.c[0] = { x, y,       q_s,  q_b,  nullptr, 128, 1, 0, 0 };
    pp.c[1] = { x, nullptr, rk_s, rk_b, prk,      64, 0, 0, 73728 };
    pp.c[2] = { x, nullptr, rv_s, rv_b, nullptr,  64, 2, 0, 110592 };
    pp.c[3] = { y, nullptr, ik_s, ik_b, pik,      64, 0, 0, 147456 };
    pp.c[4] = { y, nullptr, iv_s, iv_b, nullptr,  64, 2, 1, 184320 };
    conv_k<16><<<dim3(2, 4, 80), 256>>>(pp);

    attn_k<<<dim3(32, 4, 2), 256, ATT_SMEM>>>(x, y, g1, g2);

    // final conv (8 oc/block, grid 256 — measured-best config)
    CPack ps = {};
    ps.c[0] = { prr, pir, sr_s, sr_b, out, 128, 0, 0, 221184 };
    conv_k<8><<<dim3(2, 4, 32), 256>>>(ps);
}